// round 10
// baseline (speedup 1.0000x reference)
#include <cuda_runtime.h>
#include <cuda_bf16.h>

#define M_NODES 50000
#define DFEAT   128
#define N_EDGE  800000
#define NPW     8     // nodes per warp in fused SpMM

// scratch for support = X @ W  (25.6 MB, static device global — no allocs)
__device__ float g_support[(size_t)M_NODES * DFEAT];

// packed fp32x2 helpers (sm_100+ FFMA2 path — ptxas never auto-fuses)
#define FMA_F32X2(d, a, b, c) \
    asm("fma.rn.f32x2 %0, %1, %2, %3;" : "=l"(d) : "l"(a), "l"(b), "l"(c))
#define PACK2(d, lo, hi) \
    asm("mov.b64 %0, {%1, %2};" : "=l"(d) : "f"(lo), "f"(hi))
#define UNPACK2(lo, hi, d) \
    asm("mov.b64 {%0, %1}, %2;" : "=f"(lo), "=f"(hi) : "l"(d))

// ---------------------------------------------------------------------------
// Kernel 1: SGEMM  g_support = X @ W    (M=50000, N=K=128)
// 128x128 block tile, BK=8, 256 threads, 8x8 microtile per thread.
// A staged in smem PRE-DUPLICATED as {a,a} u64 pairs (read = bare LDS.64);
// B pairs read directly as ulonglong2 (adjacent floats = packed f32x2 operand).
// => inner loop is 32 FFMA2 + 10 LDS, zero pack MOVs.
// ---------------------------------------------------------------------------
__global__ __launch_bounds__(256) void gemm_kernel(const float* __restrict__ A,
                                                   const float* __restrict__ B) {
    __shared__ unsigned long long As2[8][128];  // 8 KB, duplicated pairs
    __shared__ float Bs[8][128];                // 4 KB

    const int tid = threadIdx.x;
    const int block_row = blockIdx.x * 128;

    const int tx = tid & 15;        // 0..15 -> 8 cols each
    const int ty = tid >> 4;        // 0..15 -> 8 rows each

    const int a_row  = tid >> 1;          // 0..127
    const int a_col4 = (tid & 1) * 4;     // 0 or 4
    const int b_row  = tid >> 5;          // 0..7
    const int b_col4 = (tid & 31) * 4;

    int g_arow = block_row + a_row;
    if (g_arow >= M_NODES) g_arow = M_NODES - 1;   // clamp; output store is guarded
    const float* Aptr = A + (long long)g_arow * DFEAT;

    // 8x4 packed accumulators (each holds cols {2j, 2j+1})
    unsigned long long acc2[8][4];
#pragma unroll
    for (int i = 0; i < 8; i++)
#pragma unroll
        for (int j = 0; j < 4; j++) acc2[i][j] = 0ull;

    // prefetch k0 = 0 tile into registers
    float4 av = *(const float4*)(Aptr + a_col4);
    float4 bv = *(const float4*)(B + (long long)b_row * DFEAT + b_col4);

    for (int k0 = 0; k0 < DFEAT; k0 += 8) {
        // stage A duplicated: As2[c][row] = {a, a}
        unsigned long long d0, d1, d2, d3;
        PACK2(d0, av.x, av.x);
        PACK2(d1, av.y, av.y);
        PACK2(d2, av.z, av.z);
        PACK2(d3, av.w, av.w);
        As2[a_col4 + 0][a_row] = d0;
        As2[a_col4 + 1][a_row] = d1;
        As2[a_col4 + 2][a_row] = d2;
        As2[a_col4 + 3][a_row] = d3;
        *(float4*)&Bs[b_row][b_col4] = bv;
        __syncthreads();

        // prefetch NEXT tile (overlaps with FMA block below)
        int kn = k0 + 8;
        if (kn < DFEAT) {
            av = *(const float4*)(Aptr + kn + a_col4);
            bv = *(const float4*)(B + (long long)(kn + b_row) * DFEAT + b_col4);
        }

#pragma unroll
        for (int kk = 0; kk < 8; kk++) {
            ulonglong2 bq0 = *(const ulonglong2*)&Bs[kk][tx * 8 + 0];
            ulonglong2 bq1 = *(const ulonglong2*)&Bs[kk][tx * 8 + 4];
            unsigned long long bp[4] = {bq0.x, bq0.y, bq1.x, bq1.y};
#pragma unroll
            for (int i = 0; i < 8; i++) {
                unsigned long long ap = As2[kk][ty * 8 + i];   // LDS.64, broadcast
#pragma unroll
                for (int j = 0; j < 4; j++)
                    FMA_F32X2(acc2[i][j], ap, bp[j], acc2[i][j]);
            }
        }
        __syncthreads();
    }

    // write 8x8 microtile (guard rows for the 50000 % 128 tail)
#pragma unroll
    for (int i = 0; i < 8; i++) {
        int row = block_row + ty * 8 + i;
        if (row < M_NODES) {
            float* dst = g_support + (long long)row * DFEAT + tx * 8;
            float4 v0, v1;
            UNPACK2(v0.x, v0.y, acc2[i][0]);
            UNPACK2(v0.z, v0.w, acc2[i][1]);
            UNPACK2(v1.x, v1.y, acc2[i][2]);
            UNPACK2(v1.z, v1.w, acc2[i][3]);
            *(float4*)(dst + 0) = v0;
            *(float4*)(dst + 4) = v1;
        }
    }
}

// ---------------------------------------------------------------------------
// Kernel 2: fused SpMM + bias, atomic-free, FIXED-BOUND edge loop.
// Each warp owns dst nodes [n0, n1); two warp-uniform binary searches give its
// full edge range [es, ee). The single for-loop over [es, ee) keeps loads
// pipelined (next iteration's dst/src/val are loop-index-addressed, independent
// of the flush branch). Run-boundary flush writes out[cur] = bias + acc with a
// plain STG.128; gap nodes (zero-degree) get bias-only rows.
// Lane l owns columns [4l, 4l+4) as a float4.
// ---------------------------------------------------------------------------
__global__ __launch_bounds__(256) void spmm_kernel(const int* __restrict__ src,
                                                   const int* __restrict__ dst,
                                                   const float* __restrict__ val,
                                                   const float* __restrict__ bias,
                                                   float* __restrict__ out) {
    const int gw   = (blockIdx.x * blockDim.x + threadIdx.x) >> 5;
    const int lane = threadIdx.x & 31;

    int n0 = gw * NPW;
    if (n0 >= M_NODES) return;
    int n1 = n0 + NPW;
    if (n1 > M_NODES) n1 = M_NODES;

    // warp-uniform lower_bound(dst, n0) and lower_bound(dst, n1)
    int es, ee;
    {
        int lo = 0, hi = N_EDGE;
        while (lo < hi) { int mid = (lo + hi) >> 1; if (dst[mid] < n0) lo = mid + 1; else hi = mid; }
        es = lo;
        hi = N_EDGE;                       // lb(n1) >= lb(n0): reuse lo
        while (lo < hi) { int mid = (lo + hi) >> 1; if (dst[mid] < n1) lo = mid + 1; else hi = mid; }
        ee = lo;
    }

    const float4* sup = (const float4*)g_support;
    const float4  bb  = ((const float4*)bias)[lane];

    int    cur = n0;
    float4 acc = make_float4(0.f, 0.f, 0.f, 0.f);

    for (int e = es; e < ee; ++e) {
        int   d = dst[e];                  // warp-uniform broadcast loads,
        int   s = src[e];                  // index-addressed -> pipelineable
        float v = val[e];
        if (d != cur) {
            float4 o = make_float4(bb.x + acc.x, bb.y + acc.y,
                                   bb.z + acc.z, bb.w + acc.w);
            *(float4*)(out + (long long)cur * DFEAT + lane * 4) = o;
            for (int g = cur + 1; g < d; ++g)          // zero-degree gap rows (rare)
                *(float4*)(out + (long long)g * DFEAT + lane * 4) = bb;
            cur = d;
            acc = make_float4(0.f, 0.f, 0.f, 0.f);
        }
        float4 sv = sup[(long long)s * (DFEAT / 4) + lane];   // 512B coalesced gather
        acc.x = fmaf(v, sv.x, acc.x);
        acc.y = fmaf(v, sv.y, acc.y);
        acc.z = fmaf(v, sv.z, acc.z);
        acc.w = fmaf(v, sv.w, acc.w);
    }
    // tail: flush last accumulated node, bias-fill the rest of the range
    {
        float4 o = make_float4(bb.x + acc.x, bb.y + acc.y,
                               bb.z + acc.z, bb.w + acc.w);
        *(float4*)(out + (long long)cur * DFEAT + lane * 4) = o;
        for (int g = cur + 1; g < n1; ++g)
            *(float4*)(out + (long long)g * DFEAT + lane * 4) = bb;
    }
}

// ---------------------------------------------------------------------------
// inputs (metadata order): x[f32 50000*128], adj_src[i32 800000],
//   adj_dst[i32 800000], adj_val[f32 800000], weight[f32 128*128], bias[f32 128]
// output: f32 50000*128
// ---------------------------------------------------------------------------
extern "C" void kernel_launch(void* const* d_in, const int* in_sizes, int n_in,
                              void* d_out, int out_size) {
    const float* x       = (const float*)d_in[0];
    const int*   adj_src = (const int*)d_in[1];
    const int*   adj_dst = (const int*)d_in[2];
    const float* adj_val = (const float*)d_in[3];
    const float* weight  = (const float*)d_in[4];
    const float* bias    = (const float*)d_in[5];
    float*       out     = (float*)d_out;

    // 1) support = X @ W
    {
        int grid = (M_NODES + 127) / 128;   // 391
        gemm_kernel<<<grid, 256>>>(x, weight);
    }
    // 2) out = bias + A_sp @ support   (fused, no atomics)
    {
        int nwarps  = (M_NODES + NPW - 1) / NPW;              // 6250
        int threads = 256;
        int grid    = (nwarps * 32 + threads - 1) / threads;  // 782
        spmm_kernel<<<grid, threads>>>(adj_src, adj_dst, adj_val, bias, out);
    }
}

// round 12
// speedup vs baseline: 1.2111x; 1.2111x over previous
#include <cuda_runtime.h>
#include <cuda_bf16.h>

#define M_NODES 50000
#define DFEAT   128
#define N_EDGE  800000
#define EPW     128   // edges per warp in SpMM

// scratch for support = X @ W  (25.6 MB, static device global — no allocs)
__device__ float g_support[(size_t)M_NODES * DFEAT];

// packed fp32x2 helpers
#define FMA_F32X2(d, a, b, c) \
    asm("fma.rn.f32x2 %0, %1, %2, %3;" : "=l"(d) : "l"(a), "l"(b), "l"(c))
#define PACK2(d, lo, hi) \
    asm("mov.b64 %0, {%1, %2};" : "=l"(d) : "f"(lo), "f"(hi))
#define UNPACK2(lo, hi, d) \
    asm("mov.b64 {%0, %1}, %2;" : "=f"(lo), "=f"(hi) : "l"(d))

// ---------------------------------------------------------------------------
// Kernel 1: SGEMM  g_support = X @ W  (+ bias-init of out rows for this tile).
// R6-measured GEMM core (47us). Each CTA also writes out[row,:]=bias for its
// 128-row range — 25.6MB of stores absorbed under FFMA-bound compute, saving
// the separate init launch.
// ---------------------------------------------------------------------------
__global__ __launch_bounds__(256) void gemm_kernel(const float* __restrict__ A,
                                                   const float* __restrict__ B,
                                                   const float* __restrict__ bias,
                                                   float* __restrict__ out) {
    __shared__ float As[8][128];   // transposed A tile
    __shared__ float Bs[8][128];

    const int tid = threadIdx.x;
    const int block_row = blockIdx.x * 128;

    // ---- bias-init prologue: out[block_row .. block_row+128) = bias ----
    {
        const float4* b4 = (const float4*)bias;
        for (int i = tid; i < 128 * 32; i += 256) {
            int row = block_row + (i >> 5);
            int c4  = i & 31;
            if (row < M_NODES)
                ((float4*)out)[(long long)row * 32 + c4] = b4[c4];
        }
    }

    const int tx = tid & 15;        // 0..15 -> 8 cols each
    const int ty = tid >> 4;        // 0..15 -> 8 rows each

    const int a_row  = tid >> 1;          // 0..127
    const int a_col4 = (tid & 1) * 4;     // 0 or 4
    const int b_row  = tid >> 5;          // 0..7
    const int b_col4 = (tid & 31) * 4;

    int g_arow = block_row + a_row;
    if (g_arow >= M_NODES) g_arow = M_NODES - 1;   // clamp; output store is guarded
    const float* Aptr = A + (long long)g_arow * DFEAT;

    // 8x4 packed accumulators (each holds cols {2j, 2j+1})
    unsigned long long acc2[8][4];
#pragma unroll
    for (int i = 0; i < 8; i++)
#pragma unroll
        for (int j = 0; j < 4; j++) acc2[i][j] = 0ull;

    // prefetch k0 = 0 tile into registers
    float4 av = *(const float4*)(Aptr + a_col4);
    float4 bv = *(const float4*)(B + (long long)b_row * DFEAT + b_col4);

    for (int k0 = 0; k0 < DFEAT; k0 += 8) {
        As[a_col4 + 0][a_row] = av.x;
        As[a_col4 + 1][a_row] = av.y;
        As[a_col4 + 2][a_row] = av.z;
        As[a_col4 + 3][a_row] = av.w;
        *(float4*)&Bs[b_row][b_col4] = bv;
        __syncthreads();

        // prefetch NEXT tile (overlaps with FMA block below)
        int kn = k0 + 8;
        if (kn < DFEAT) {
            av = *(const float4*)(Aptr + kn + a_col4);
            bv = *(const float4*)(B + (long long)(kn + b_row) * DFEAT + b_col4);
        }

#pragma unroll
        for (int kk = 0; kk < 8; kk++) {
            float4 a0 = *(const float4*)&As[kk][ty * 8 + 0];
            float4 a1 = *(const float4*)&As[kk][ty * 8 + 4];
            float4 b0 = *(const float4*)&Bs[kk][tx * 8 + 0];
            float4 b1 = *(const float4*)&Bs[kk][tx * 8 + 4];

            unsigned long long bp[4];
            PACK2(bp[0], b0.x, b0.y);
            PACK2(bp[1], b0.z, b0.w);
            PACK2(bp[2], b1.x, b1.y);
            PACK2(bp[3], b1.z, b1.w);

            float a[8] = {a0.x, a0.y, a0.z, a0.w, a1.x, a1.y, a1.z, a1.w};
#pragma unroll
            for (int i = 0; i < 8; i++) {
                unsigned long long ap;
                PACK2(ap, a[i], a[i]);
#pragma unroll
                for (int j = 0; j < 4; j++)
                    FMA_F32X2(acc2[i][j], ap, bp[j], acc2[i][j]);
            }
        }
        __syncthreads();
    }

    // write 8x8 microtile (guard rows for the 50000 % 128 tail)
#pragma unroll
    for (int i = 0; i < 8; i++) {
        int row = block_row + ty * 8 + i;
        if (row < M_NODES) {
            float* dst = g_support + (long long)row * DFEAT + tx * 8;
            float4 v0, v1;
            UNPACK2(v0.x, v0.y, acc2[i][0]);
            UNPACK2(v0.z, v0.w, acc2[i][1]);
            UNPACK2(v1.x, v1.y, acc2[i][2]);
            UNPACK2(v1.z, v1.w, acc2[i][3]);
            *(float4*)(dst + 0) = v0;
            *(float4*)(dst + 4) = v1;
        }
    }
}

// ---------------------------------------------------------------------------
// Kernel 2: SpMM scatter — R3's measured-38us structure, UNCHANGED.
// FLAT loop body (no nested loops!) so ptxas unrolls and batches the LDGs;
// run-boundary flushes via fire-and-forget atomicAdd (RED). out already holds
// bias (written by gemm_kernel's prologue). Lane l owns cols [4l, 4l+4).
// ---------------------------------------------------------------------------
__global__ __launch_bounds__(256) void spmm_kernel(const int* __restrict__ src,
                                                   const int* __restrict__ dst,
                                                   const float* __restrict__ val,
                                                   float* __restrict__ out) {
    const int gw   = (blockIdx.x * blockDim.x + threadIdx.x) >> 5;
    const int lane = threadIdx.x & 31;

    int e0 = gw * EPW;
    if (e0 >= N_EDGE) return;
    int e1 = e0 + EPW;
    if (e1 > N_EDGE) e1 = N_EDGE;

    const float4* sup = (const float4*)g_support;

    float4 acc = make_float4(0.f, 0.f, 0.f, 0.f);
    int cur = dst[e0];

    for (int e = e0; e < e1; ++e) {
        int d = dst[e];                       // warp-uniform broadcast
        if (d != cur) {
            float* o = out + (long long)cur * DFEAT + lane * 4;
            atomicAdd(o + 0, acc.x);
            atomicAdd(o + 1, acc.y);
            atomicAdd(o + 2, acc.z);
            atomicAdd(o + 3, acc.w);
            acc = make_float4(0.f, 0.f, 0.f, 0.f);
            cur = d;
        }
        float v = val[e];                     // warp-uniform
        int   s = src[e];                     // warp-uniform
        float4 sv = sup[(long long)s * (DFEAT / 4) + lane];  // 512B coalesced gather (L2-hot)
        acc.x = fmaf(v, sv.x, acc.x);
        acc.y = fmaf(v, sv.y, acc.y);
        acc.z = fmaf(v, sv.z, acc.z);
        acc.w = fmaf(v, sv.w, acc.w);
    }
    float* o = out + (long long)cur * DFEAT + lane * 4;
    atomicAdd(o + 0, acc.x);
    atomicAdd(o + 1, acc.y);
    atomicAdd(o + 2, acc.z);
    atomicAdd(o + 3, acc.w);
}

// ---------------------------------------------------------------------------
// inputs (metadata order): x[f32 50000*128], adj_src[i32 800000],
//   adj_dst[i32 800000], adj_val[f32 800000], weight[f32 128*128], bias[f32 128]
// output: f32 50000*128
// ---------------------------------------------------------------------------
extern "C" void kernel_launch(void* const* d_in, const int* in_sizes, int n_in,
                              void* d_out, int out_size) {
    const float* x       = (const float*)d_in[0];
    const int*   adj_src = (const int*)d_in[1];
    const int*   adj_dst = (const int*)d_in[2];
    const float* adj_val = (const float*)d_in[3];
    const float* weight  = (const float*)d_in[4];
    const float* bias    = (const float*)d_in[5];
    float*       out     = (float*)d_out;

    // 1) support = X @ W   (+ out = bias, fused prologue)
    {
        int grid = (M_NODES + 127) / 128;   // 391
        gemm_kernel<<<grid, 256>>>(x, weight, bias, out);
    }
    // 2) out += A_sp @ support
    {
        int nwarps  = (N_EDGE + EPW - 1) / EPW;               // 6250
        int threads = 256;
        int grid    = (nwarps * 32 + threads - 1) / threads;  // 782
        spmm_kernel<<<grid, threads>>>(adj_src, adj_dst, adj_val, out);
    }
}

// round 16
// speedup vs baseline: 1.2383x; 1.0225x over previous
#include <cuda_runtime.h>
#include <cuda_bf16.h>

#define M_NODES 50000
#define DFEAT   128
#define N_EDGE  800000
#define EPW     128    // edges per warp in SpMM
#define EPB     1024   // edges per block (8 warps)

// scratch for support = X @ W  (25.6 MB, static device global — no allocs)
__device__ float g_support[(size_t)M_NODES * DFEAT];

// packed fp32x2 helpers
#define FMA_F32X2(d, a, b, c) \
    asm("fma.rn.f32x2 %0, %1, %2, %3;" : "=l"(d) : "l"(a), "l"(b), "l"(c))
#define PACK2(d, lo, hi) \
    asm("mov.b64 %0, {%1, %2};" : "=l"(d) : "f"(lo), "f"(hi))
#define UNPACK2(lo, hi, d) \
    asm("mov.b64 {%0, %1}, %2;" : "=f"(lo), "=f"(hi) : "l"(d))

// ---------------------------------------------------------------------------
// Kernel 1: SGEMM  g_support = X @ W  (+ bias-init of out rows) — UNCHANGED
// from R12 (measured 50.2us incl. prologue; at fp32 FFMA roofline).
// ---------------------------------------------------------------------------
__global__ __launch_bounds__(256) void gemm_kernel(const float* __restrict__ A,
                                                   const float* __restrict__ B,
                                                   const float* __restrict__ bias,
                                                   float* __restrict__ out) {
    __shared__ float As[8][128];   // transposed A tile
    __shared__ float Bs[8][128];

    const int tid = threadIdx.x;
    const int block_row = blockIdx.x * 128;

    // ---- bias-init prologue: out[block_row .. block_row+128) = bias ----
    {
        const float4* b4 = (const float4*)bias;
        for (int i = tid; i < 128 * 32; i += 256) {
            int row = block_row + (i >> 5);
            int c4  = i & 31;
            if (row < M_NODES)
                ((float4*)out)[(long long)row * 32 + c4] = b4[c4];
        }
    }

    const int tx = tid & 15;
    const int ty = tid >> 4;

    const int a_row  = tid >> 1;
    const int a_col4 = (tid & 1) * 4;
    const int b_row  = tid >> 5;
    const int b_col4 = (tid & 31) * 4;

    int g_arow = block_row + a_row;
    if (g_arow >= M_NODES) g_arow = M_NODES - 1;
    const float* Aptr = A + (long long)g_arow * DFEAT;

    unsigned long long acc2[8][4];
#pragma unroll
    for (int i = 0; i < 8; i++)
#pragma unroll
        for (int j = 0; j < 4; j++) acc2[i][j] = 0ull;

    float4 av = *(const float4*)(Aptr + a_col4);
    float4 bv = *(const float4*)(B + (long long)b_row * DFEAT + b_col4);

    for (int k0 = 0; k0 < DFEAT; k0 += 8) {
        As[a_col4 + 0][a_row] = av.x;
        As[a_col4 + 1][a_row] = av.y;
        As[a_col4 + 2][a_row] = av.z;
        As[a_col4 + 3][a_row] = av.w;
        *(float4*)&Bs[b_row][b_col4] = bv;
        __syncthreads();

        int kn = k0 + 8;
        if (kn < DFEAT) {
            av = *(const float4*)(Aptr + kn + a_col4);
            bv = *(const float4*)(B + (long long)(kn + b_row) * DFEAT + b_col4);
        }

#pragma unroll
        for (int kk = 0; kk < 8; kk++) {
            float4 a0 = *(const float4*)&As[kk][ty * 8 + 0];
            float4 a1 = *(const float4*)&As[kk][ty * 8 + 4];
            float4 b0 = *(const float4*)&Bs[kk][tx * 8 + 0];
            float4 b1 = *(const float4*)&Bs[kk][tx * 8 + 4];

            unsigned long long bp[4];
            PACK2(bp[0], b0.x, b0.y);
            PACK2(bp[1], b0.z, b0.w);
            PACK2(bp[2], b1.x, b1.y);
            PACK2(bp[3], b1.z, b1.w);

            float a[8] = {a0.x, a0.y, a0.z, a0.w, a1.x, a1.y, a1.z, a1.w};
#pragma unroll
            for (int i = 0; i < 8; i++) {
                unsigned long long ap;
                PACK2(ap, a[i], a[i]);
#pragma unroll
                for (int j = 0; j < 4; j++)
                    FMA_F32X2(acc2[i][j], ap, bp[j], acc2[i][j]);
            }
        }
        __syncthreads();
    }

#pragma unroll
    for (int i = 0; i < 8; i++) {
        int row = block_row + ty * 8 + i;
        if (row < M_NODES) {
            float* dst = g_support + (long long)row * DFEAT + tx * 8;
            float4 v0, v1;
            UNPACK2(v0.x, v0.y, acc2[i][0]);
            UNPACK2(v0.z, v0.w, acc2[i][1]);
            UNPACK2(v1.x, v1.y, acc2[i][2]);
            UNPACK2(v1.z, v1.w, acc2[i][3]);
            *(float4*)(dst + 0) = v0;
            *(float4*)(dst + 4) = v1;
        }
    }
}

// ---------------------------------------------------------------------------
// Kernel 2: SpMM scatter with SMEM-STAGED edge streams.
// The block cooperatively loads its 1024 edges' src/dst/val via wide coalesced
// LDGs (huge MLP), then each warp's flat inner loop reads indices from smem
// (LDS, no L2 round trip) and issues only the float4 gather to L2.
// Run-boundary flushes via fire-and-forget atomicAdd (out already = bias).
// Lane l owns cols [4l, 4l+4).
// ---------------------------------------------------------------------------
__global__ __launch_bounds__(256) void spmm_kernel(const int* __restrict__ src,
                                                   const int* __restrict__ dst,
                                                   const float* __restrict__ val,
                                                   float* __restrict__ out) {
    __shared__ int   s_src[EPB];
    __shared__ int   s_dst[EPB];
    __shared__ float s_val[EPB];

    const int tid  = threadIdx.x;
    const int base = blockIdx.x * EPB;

    // ---- cooperative staging: 4 edges per thread, vectorized ----
    {
        int i4 = tid * 4;
        int e  = base + i4;
        if (e + 3 < N_EDGE) {
            *(int4*)&s_src[i4]   = *(const int4*)(src + e);
            *(int4*)&s_dst[i4]   = *(const int4*)(dst + e);
            *(float4*)&s_val[i4] = *(const float4*)(val + e);
        } else {
#pragma unroll
            for (int k = 0; k < 4; k++) {
                if (e + k < N_EDGE) {
                    s_src[i4 + k] = src[e + k];
                    s_dst[i4 + k] = dst[e + k];
                    s_val[i4 + k] = val[e + k];
                }
            }
        }
    }
    __syncthreads();

    const int wid  = tid >> 5;
    const int lane = tid & 31;

    int l0 = wid * EPW;            // local edge offset of this warp
    int g0 = base + l0;            // global edge offset
    if (g0 >= N_EDGE) return;
    int cnt = N_EDGE - g0;
    if (cnt > EPW) cnt = EPW;

    const float4* sup = (const float4*)g_support;

    float4 acc = make_float4(0.f, 0.f, 0.f, 0.f);
    int cur = s_dst[l0];

#pragma unroll 4
    for (int j = 0; j < cnt; ++j) {
        int   d = s_dst[l0 + j];          // LDS broadcast (cheap)
        int   s = s_src[l0 + j];
        float v = s_val[l0 + j];
        if (d != cur) {
            float* o = out + (long long)cur * DFEAT + lane * 4;
            atomicAdd(o + 0, acc.x);
            atomicAdd(o + 1, acc.y);
            atomicAdd(o + 2, acc.z);
            atomicAdd(o + 3, acc.w);
            acc = make_float4(0.f, 0.f, 0.f, 0.f);
            cur = d;
        }
        float4 sv = sup[(long long)s * (DFEAT / 4) + lane];   // 512B coalesced gather (L2-hot)
        acc.x = fmaf(v, sv.x, acc.x);
        acc.y = fmaf(v, sv.y, acc.y);
        acc.z = fmaf(v, sv.z, acc.z);
        acc.w = fmaf(v, sv.w, acc.w);
    }
    float* o = out + (long long)cur * DFEAT + lane * 4;
    atomicAdd(o + 0, acc.x);
    atomicAdd(o + 1, acc.y);
    atomicAdd(o + 2, acc.z);
    atomicAdd(o + 3, acc.w);
}

// ---------------------------------------------------------------------------
// inputs (metadata order): x[f32 50000*128], adj_src[i32 800000],
//   adj_dst[i32 800000], adj_val[f32 800000], weight[f32 128*128], bias[f32 128]
// output: f32 50000*128
// ---------------------------------------------------------------------------
extern "C" void kernel_launch(void* const* d_in, const int* in_sizes, int n_in,
                              void* d_out, int out_size) {
    const float* x       = (const float*)d_in[0];
    const int*   adj_src = (const int*)d_in[1];
    const int*   adj_dst = (const int*)d_in[2];
    const float* adj_val = (const float*)d_in[3];
    const float* weight  = (const float*)d_in[4];
    const float* bias    = (const float*)d_in[5];
    float*       out     = (float*)d_out;

    // 1) support = X @ W   (+ out = bias, fused prologue)
    {
        int grid = (M_NODES + 127) / 128;   // 391
        gemm_kernel<<<grid, 256>>>(x, weight, bias, out);
    }
    // 2) out += A_sp @ support
    {
        int grid = (N_EDGE + EPB - 1) / EPB;   // 782
        spmm_kernel<<<grid, 256>>>(adj_src, adj_dst, adj_val, out);
    }
}